// round 3
// baseline (speedup 1.0000x reference)
#include <cuda_runtime.h>
#include <math.h>

// Problem constants (fixed by the dataset)
#define BATCH   2
#define SQ      2048
#define SKV     2048
#define DIM     1024
#define HEADS   16
#define DHEAD   64
#define INNER   1024            // HEADS * DHEAD
#define MQ      (BATCH * SQ)    // 4096 rows for Q-side GEMMs
#define MKV     (BATCH * SKV)   // 4096 rows for KV-side GEMM

// Scratch (no cudaMalloc allowed): Q [4096,1024], KV [4096,2048] (K|V), O [4096,1024]
__device__ float g_q [MQ  * INNER];
__device__ float g_kv[MKV * 2 * INNER];
__device__ float g_o [MQ  * INNER];

// ---------------------------------------------------------------------------
// Classic 128x128x8 SGEMM, 256 threads, 8x8 per thread. Row-major A[M,K],
// B[K,N] (with ldb), C[M,N] (with ldc). Optional bias added per column.
// All dims here are multiples of 128/8 so no bounds checks.
// ---------------------------------------------------------------------------
__global__ __launch_bounds__(256) void sgemm128(
    const float* __restrict__ A, const float* __restrict__ Bm,
    float* __restrict__ C, const float* __restrict__ bias,
    int K, int lda, int ldb, int ldc)
{
    __shared__ float As[8][128];
    __shared__ float Bs[8][128];

    const int tid  = threadIdx.x;
    const int brow = blockIdx.y * 128;
    const int bcol = blockIdx.x * 128;

    const int arow   = tid >> 1;          // 0..127
    const int acol   = (tid & 1) * 4;     // 0 or 4
    const int browb  = tid >> 5;          // 0..7
    const int bcolb  = (tid & 31) * 4;    // 0..124

    const int ty = tid >> 4;              // 0..15
    const int tx = tid & 15;              // 0..15

    float acc[8][8];
    #pragma unroll
    for (int i = 0; i < 8; i++)
        #pragma unroll
        for (int j = 0; j < 8; j++) acc[i][j] = 0.f;

    const float* Aptr = A  + (size_t)(brow + arow) * lda + acol;
    const float* Bptr = Bm + (size_t)browb * ldb + bcol + bcolb;

    for (int k0 = 0; k0 < K; k0 += 8) {
        float4 av = *(const float4*)(Aptr + k0);
        float4 bv = *(const float4*)(Bptr + (size_t)k0 * ldb);

        As[acol + 0][arow] = av.x;
        As[acol + 1][arow] = av.y;
        As[acol + 2][arow] = av.z;
        As[acol + 3][arow] = av.w;
        *(float4*)&Bs[browb][bcolb] = bv;
        __syncthreads();

        #pragma unroll
        for (int k = 0; k < 8; k++) {
            float a[8], b[8];
            #pragma unroll
            for (int i = 0; i < 8; i++) a[i] = As[k][ty * 8 + i];
            #pragma unroll
            for (int j = 0; j < 8; j++) b[j] = Bs[k][tx * 8 + j];
            #pragma unroll
            for (int i = 0; i < 8; i++)
                #pragma unroll
                for (int j = 0; j < 8; j++)
                    acc[i][j] += a[i] * b[j];
        }
        __syncthreads();
    }

    #pragma unroll
    for (int i = 0; i < 8; i++) {
        const int r = brow + ty * 8 + i;
        float* crow = C + (size_t)r * ldc + bcol + tx * 8;
        #pragma unroll
        for (int j = 0; j < 8; j += 4) {
            float4 v;
            v.x = acc[i][j + 0]; v.y = acc[i][j + 1];
            v.z = acc[i][j + 2]; v.w = acc[i][j + 3];
            if (bias) {
                const int c0 = bcol + tx * 8 + j;
                v.x += bias[c0 + 0]; v.y += bias[c0 + 1];
                v.z += bias[c0 + 2]; v.w += bias[c0 + 3];
            }
            *(float4*)(crow + j) = v;
        }
    }
}

// ---------------------------------------------------------------------------
// Flash-style attention, fp32. One block = (b, h, 64-query tile); 64 threads,
// one thread per query row. KV streamed through smem in 32-row tiles.
// Q layout: [B*SQ, INNER] (head h at cols h*64..). KV layout: [B*SKV, 2*INNER]
// (K at cols h*64, V at cols INNER + h*64).
// ---------------------------------------------------------------------------
__global__ __launch_bounds__(64) void attn_kernel(
    const float* __restrict__ Q, const float* __restrict__ KV,
    float* __restrict__ O)
{
    const int qt = blockIdx.x;   // 0..31
    const int h  = blockIdx.y;   // 0..15
    const int b  = blockIdx.z;   // 0..1
    const int t  = threadIdx.x;  // 0..63

    __shared__ float Ks[32][64];
    __shared__ float Vs[32][64];

    const float scale = 0.125f;  // 64^-0.5

    // Load this thread's query row into registers
    float q[64];
    {
        const float* qrow = Q + ((size_t)b * SQ + qt * 64 + t) * INNER + h * DHEAD;
        #pragma unroll
        for (int d = 0; d < 64; d += 4) {
            float4 v = *(const float4*)(qrow + d);
            q[d + 0] = v.x; q[d + 1] = v.y; q[d + 2] = v.z; q[d + 3] = v.w;
        }
    }

    float m = -INFINITY, l = 0.f;
    float o[64];
    #pragma unroll
    for (int d = 0; d < 64; d++) o[d] = 0.f;

    for (int kv0 = 0; kv0 < SKV; kv0 += 32) {
        __syncthreads();
        // cooperative tile load: 32 rows x 16 float4 for K and V each
        for (int i = t; i < 32 * 16; i += 64) {
            const int j  = i >> 4;
            const int d4 = i & 15;
            const size_t base = ((size_t)b * SKV + kv0 + j) * (2 * INNER) + h * DHEAD;
            ((float4*)Ks[j])[d4] = *(const float4*)(KV + base + d4 * 4);
            ((float4*)Vs[j])[d4] = *(const float4*)(KV + base + INNER + d4 * 4);
        }
        __syncthreads();

        // scores for this tile
        float s[32];
        float tmax = -INFINITY;
        #pragma unroll
        for (int j = 0; j < 32; j++) {
            float acc = 0.f;
            #pragma unroll
            for (int d = 0; d < 64; d++) acc += q[d] * Ks[j][d];
            s[j] = acc * scale;
            tmax = fmaxf(tmax, s[j]);
        }

        // online softmax rescale (once per tile)
        const float mnew = fmaxf(m, tmax);
        const float c = __expf(m - mnew);   // 0 on first tile (m = -inf)
        l *= c;
        #pragma unroll
        for (int d = 0; d < 64; d++) o[d] *= c;
        m = mnew;

        #pragma unroll
        for (int j = 0; j < 32; j++) {
            const float p = __expf(s[j] - m);
            l += p;
            #pragma unroll
            for (int d = 0; d < 64; d++) o[d] += p * Vs[j][d];
        }
    }

    const float inv = 1.f / l;
    float* orow = O + ((size_t)b * SQ + qt * 64 + t) * INNER + h * DHEAD;
    #pragma unroll
    for (int d = 0; d < 64; d += 4) {
        float4 v;
        v.x = o[d + 0] * inv; v.y = o[d + 1] * inv;
        v.z = o[d + 2] * inv; v.w = o[d + 3] * inv;
        *(float4*)(orow + d) = v;
    }
}

// ---------------------------------------------------------------------------
// kernel_launch: x_q, x_kv, W_qkv, W_out, b_out  ->  out [B, SQ, DIM] fp32
// ---------------------------------------------------------------------------
extern "C" void kernel_launch(void* const* d_in, const int* in_sizes, int n_in,
                              void* d_out, int out_size)
{
    const float* x_q   = (const float*)d_in[0];
    const float* x_kv  = (const float*)d_in[1];
    const float* W_qkv = (const float*)d_in[2];  // [1024, 3072]
    const float* W_out = (const float*)d_in[3];  // [1024, 1024]
    const float* b_out = (const float*)d_in[4];  // [1024]
    float* out = (float*)d_out;

    float *q, *kv, *o;
    cudaGetSymbolAddress((void**)&q,  g_q);
    cudaGetSymbolAddress((void**)&kv, g_kv);
    cudaGetSymbolAddress((void**)&o,  g_o);

    // Q = x_q @ W_qkv[:, 0:1024]            -> [4096, 1024]
    sgemm128<<<dim3(INNER / 128, MQ / 128), 256>>>(
        x_q, W_qkv, q, nullptr, DIM, DIM, 3 * INNER, INNER);

    // KV = x_kv @ W_qkv[:, 1024:3072]       -> [4096, 2048]  (K | V)
    sgemm128<<<dim3(2 * INNER / 128, MKV / 128), 256>>>(
        x_kv, W_qkv + INNER, kv, nullptr, DIM, DIM, 3 * INNER, 2 * INNER);

    // attention                              -> O [4096, 1024]
    attn_kernel<<<dim3(SQ / 64, HEADS, BATCH), 64>>>(q, kv, o);

    // out = O @ W_out + b_out                -> [4096, 1024]
    sgemm128<<<dim3(DIM / 128, MQ / 128), 256>>>(
        o, W_out, out, b_out, INNER, INNER, DIM, DIM);
}

// round 4
// speedup vs baseline: 1.0044x; 1.0044x over previous
#include <cuda_runtime.h>
#include <math.h>

// Problem constants (fixed by the dataset)
#define BATCH   2
#define SQ      2048
#define SKV     2048
#define DIM     1024
#define HEADS   16
#define DHEAD   64
#define INNER   1024            // HEADS * DHEAD
#define MQ      (BATCH * SQ)    // 4096 rows for Q-side GEMMs
#define MKV     (BATCH * SKV)   // 4096 rows for KV-side GEMM

// Scratch (no cudaMalloc allowed): Q [4096,1024], KV [4096,2048] (K|V), O [4096,1024]
__device__ float g_q [MQ  * INNER];
__device__ float g_kv[MKV * 2 * INNER];
__device__ float g_o [MQ  * INNER];

// ---------------------------------------------------------------------------
// Classic 128x128x8 SGEMM, 256 threads, 8x8 per thread. Row-major A[M,K],
// B[K,N] (with ldb), C[M,N] (with ldc). Optional bias added per column.
// All dims here are multiples of 128/8 so no bounds checks.
// ---------------------------------------------------------------------------
__global__ __launch_bounds__(256) void sgemm128(
    const float* __restrict__ A, const float* __restrict__ Bm,
    float* __restrict__ C, const float* __restrict__ bias,
    int K, int lda, int ldb, int ldc)
{
    __shared__ float As[8][128];
    __shared__ float Bs[8][128];

    const int tid  = threadIdx.x;
    const int brow = blockIdx.y * 128;
    const int bcol = blockIdx.x * 128;

    const int arow   = tid >> 1;          // 0..127
    const int acol   = (tid & 1) * 4;     // 0 or 4
    const int browb  = tid >> 5;          // 0..7
    const int bcolb  = (tid & 31) * 4;    // 0..124

    const int ty = tid >> 4;              // 0..15
    const int tx = tid & 15;              // 0..15

    float acc[8][8];
    #pragma unroll
    for (int i = 0; i < 8; i++)
        #pragma unroll
        for (int j = 0; j < 8; j++) acc[i][j] = 0.f;

    const float* Aptr = A  + (size_t)(brow + arow) * lda + acol;
    const float* Bptr = Bm + (size_t)browb * ldb + bcol + bcolb;

    for (int k0 = 0; k0 < K; k0 += 8) {
        float4 av = *(const float4*)(Aptr + k0);
        float4 bv = *(const float4*)(Bptr + (size_t)k0 * ldb);

        As[acol + 0][arow] = av.x;
        As[acol + 1][arow] = av.y;
        As[acol + 2][arow] = av.z;
        As[acol + 3][arow] = av.w;
        *(float4*)&Bs[browb][bcolb] = bv;
        __syncthreads();

        #pragma unroll
        for (int k = 0; k < 8; k++) {
            float a[8], b[8];
            #pragma unroll
            for (int i = 0; i < 8; i++) a[i] = As[k][ty * 8 + i];
            #pragma unroll
            for (int j = 0; j < 8; j++) b[j] = Bs[k][tx * 8 + j];
            #pragma unroll
            for (int i = 0; i < 8; i++)
                #pragma unroll
                for (int j = 0; j < 8; j++)
                    acc[i][j] += a[i] * b[j];
        }
        __syncthreads();
    }

    #pragma unroll
    for (int i = 0; i < 8; i++) {
        const int r = brow + ty * 8 + i;
        float* crow = C + (size_t)r * ldc + bcol + tx * 8;
        #pragma unroll
        for (int j = 0; j < 8; j += 4) {
            float4 v;
            v.x = acc[i][j + 0]; v.y = acc[i][j + 1];
            v.z = acc[i][j + 2]; v.w = acc[i][j + 3];
            if (bias) {
                const int c0 = bcol + tx * 8 + j;
                v.x += bias[c0 + 0]; v.y += bias[c0 + 1];
                v.z += bias[c0 + 2]; v.w += bias[c0 + 3];
            }
            *(float4*)(crow + j) = v;
        }
    }
}

// ---------------------------------------------------------------------------
// Flash-style attention, fp32. One block = (b, h, 64-query tile); 64 threads,
// one thread per query row. KV streamed through smem in 32-row tiles.
// Q layout: [B*SQ, INNER] (head h at cols h*64..). KV layout: [B*SKV, 2*INNER]
// (K at cols h*64, V at cols INNER + h*64).
// ---------------------------------------------------------------------------
__global__ __launch_bounds__(64) void attn_kernel(
    const float* __restrict__ Q, const float* __restrict__ KV,
    float* __restrict__ O)
{
    const int qt = blockIdx.x;   // 0..31
    const int h  = blockIdx.y;   // 0..15
    const int b  = blockIdx.z;   // 0..1
    const int t  = threadIdx.x;  // 0..63

    __shared__ float Ks[32][64];
    __shared__ float Vs[32][64];

    const float scale = 0.125f;  // 64^-0.5

    // Load this thread's query row into registers
    float q[64];
    {
        const float* qrow = Q + ((size_t)b * SQ + qt * 64 + t) * INNER + h * DHEAD;
        #pragma unroll
        for (int d = 0; d < 64; d += 4) {
            float4 v = *(const float4*)(qrow + d);
            q[d + 0] = v.x; q[d + 1] = v.y; q[d + 2] = v.z; q[d + 3] = v.w;
        }
    }

    float m = -INFINITY, l = 0.f;
    float o[64];
    #pragma unroll
    for (int d = 0; d < 64; d++) o[d] = 0.f;

    for (int kv0 = 0; kv0 < SKV; kv0 += 32) {
        __syncthreads();
        // cooperative tile load: 32 rows x 16 float4 for K and V each
        for (int i = t; i < 32 * 16; i += 64) {
            const int j  = i >> 4;
            const int d4 = i & 15;
            const size_t base = ((size_t)b * SKV + kv0 + j) * (2 * INNER) + h * DHEAD;
            ((float4*)Ks[j])[d4] = *(const float4*)(KV + base + d4 * 4);
            ((float4*)Vs[j])[d4] = *(const float4*)(KV + base + INNER + d4 * 4);
        }
        __syncthreads();

        // scores for this tile
        float s[32];
        float tmax = -INFINITY;
        #pragma unroll
        for (int j = 0; j < 32; j++) {
            float acc = 0.f;
            #pragma unroll
            for (int d = 0; d < 64; d++) acc += q[d] * Ks[j][d];
            s[j] = acc * scale;
            tmax = fmaxf(tmax, s[j]);
        }

        // online softmax rescale (once per tile)
        const float mnew = fmaxf(m, tmax);
        const float c = __expf(m - mnew);   // 0 on first tile (m = -inf)
        l *= c;
        #pragma unroll
        for (int d = 0; d < 64; d++) o[d] *= c;
        m = mnew;

        #pragma unroll
        for (int j = 0; j < 32; j++) {
            const float p = __expf(s[j] - m);
            l += p;
            #pragma unroll
            for (int d = 0; d < 64; d++) o[d] += p * Vs[j][d];
        }
    }

    const float inv = 1.f / l;
    float* orow = O + ((size_t)b * SQ + qt * 64 + t) * INNER + h * DHEAD;
    #pragma unroll
    for (int d = 0; d < 64; d += 4) {
        float4 v;
        v.x = o[d + 0] * inv; v.y = o[d + 1] * inv;
        v.z = o[d + 2] * inv; v.w = o[d + 3] * inv;
        *(float4*)(orow + d) = v;
    }
}

// ---------------------------------------------------------------------------
// kernel_launch: x_q, x_kv, W_qkv, W_out, b_out  ->  out [B, SQ, DIM] fp32
// ---------------------------------------------------------------------------
extern "C" void kernel_launch(void* const* d_in, const int* in_sizes, int n_in,
                              void* d_out, int out_size)
{
    const float* x_q   = (const float*)d_in[0];
    const float* x_kv  = (const float*)d_in[1];
    const float* W_qkv = (const float*)d_in[2];  // [1024, 3072]
    const float* W_out = (const float*)d_in[3];  // [1024, 1024]
    const float* b_out = (const float*)d_in[4];  // [1024]
    float* out = (float*)d_out;

    float *q, *kv, *o;
    cudaGetSymbolAddress((void**)&q,  g_q);
    cudaGetSymbolAddress((void**)&kv, g_kv);
    cudaGetSymbolAddress((void**)&o,  g_o);

    // Q = x_q @ W_qkv[:, 0:1024]            -> [4096, 1024]
    sgemm128<<<dim3(INNER / 128, MQ / 128), 256>>>(
        x_q, W_qkv, q, nullptr, DIM, DIM, 3 * INNER, INNER);

    // KV = x_kv @ W_qkv[:, 1024:3072]       -> [4096, 2048]  (K | V)
    sgemm128<<<dim3(2 * INNER / 128, MKV / 128), 256>>>(
        x_kv, W_qkv + INNER, kv, nullptr, DIM, DIM, 3 * INNER, 2 * INNER);

    // attention                              -> O [4096, 1024]
    attn_kernel<<<dim3(SQ / 64, HEADS, BATCH), 64>>>(q, kv, o);

    // out = O @ W_out + b_out                -> [4096, 1024]
    sgemm128<<<dim3(DIM / 128, MQ / 128), 256>>>(
        o, W_out, out, b_out, INNER, INNER, DIM, DIM);
}

// round 6
// speedup vs baseline: 1.2941x; 1.2884x over previous
#include <cuda_runtime.h>
#include <cstdint>
#include <math.h>

// Problem constants (fixed by the dataset)
#define BATCH   2
#define SQ      2048
#define SKV     2048
#define DIM     1024
#define HEADS   16
#define DHEAD   64
#define INNER   1024            // HEADS * DIM_HEAD
#define MQ      (BATCH * SQ)    // 4096
#define MKV     (BATCH * SKV)   // 4096

// Scratch (no cudaMalloc allowed)
__device__ float g_q  [MQ  * INNER];          // 16 MB
__device__ float g_kv [MKV * 2 * INNER];      // 32 MB (K | V)
__device__ float g_o  [MQ  * INNER];          // 16 MB

// fp32 -> tf32 (round-to-nearest) as raw bits
__device__ __forceinline__ uint32_t tf32r(float x) {
    uint32_t r;
    asm("cvt.rna.tf32.f32 %0, %1;" : "=r"(r) : "f"(x));
    return r;
}

// warp-level tf32 MMA: D[16x8] += A[16x8] * B[8x8]  (row.col)
__device__ __forceinline__ void mma_tf32(float* d, const uint32_t* a, const uint32_t* b) {
    asm volatile(
        "mma.sync.aligned.m16n8k8.row.col.f32.tf32.tf32.f32 "
        "{%0,%1,%2,%3}, {%4,%5,%6,%7}, {%8,%9}, {%0,%1,%2,%3};"
        : "+f"(d[0]), "+f"(d[1]), "+f"(d[2]), "+f"(d[3])
        : "r"(a[0]), "r"(a[1]), "r"(a[2]), "r"(a[3]), "r"(b[0]), "r"(b[1]));
}

// ===========================================================================
// tf32 tensor-core GEMM: C[M,N] = A[M,K] @ B[K,N] (+ bias)
// A,B,C row-major with lda/ldb/ldc. CTA tile 128x128, K-tile 32,
// 256 threads (8 warps, 2x4), warp tile 64x32, double-buffered SMEM.
// All dims multiples of 128/32.
// ===========================================================================
#define ALD 36                 // A smem row pitch (floats): conflict-free frags
#define BLD 136                // B smem row pitch (floats): conflict-free frags
#define A_TILE_F (128 * ALD)   // 4608 floats
#define B_TILE_F (32 * BLD)    // 4352 floats
#define SM_FLOATS (2 * (A_TILE_F + B_TILE_F))
#define SM_BYTES  (SM_FLOATS * 4)   // 71680

__global__ __launch_bounds__(256) void gemm_tf32mma(
    const float* __restrict__ A, const float* __restrict__ B,
    float* __restrict__ C, const float* __restrict__ bias,
    int K, int lda, int ldb, int ldc)
{
    extern __shared__ float smem[];
    float* As[2] = { smem,                         smem + A_TILE_F + B_TILE_F };
    float* Bs[2] = { smem + A_TILE_F,              smem + 2 * A_TILE_F + B_TILE_F };

    const int tid  = threadIdx.x;
    const int wid  = tid >> 5;
    const int lane = tid & 31;
    const int g    = lane >> 2;      // groupID 0..7
    const int t    = lane & 3;       // thread-in-group 0..3
    const int wrow = (wid & 1) * 64; // warp row offset in CTA tile
    const int wcol = (wid >> 1) * 32;// warp col offset in CTA tile

    const int brow = blockIdx.y * 128;
    const int bcol = blockIdx.x * 128;

    float acc[4][4][4];
    #pragma unroll
    for (int i = 0; i < 4; i++)
        #pragma unroll
        for (int j = 0; j < 4; j++)
            #pragma unroll
            for (int r = 0; r < 4; r++) acc[i][j][r] = 0.f;

    const float* Ab = A + (size_t)brow * lda;
    const float* Bb = B + bcol;

    // ---- tile load helpers (global -> regs -> smem with tf32 rounding) ----
    // A tile: 128 rows x 32 cols = 1024 float4, 4 per thread
    // B tile:  32 rows x 128 cols = 1024 float4, 4 per thread
    auto load_regs = [&](int k0, float4* pa, float4* pb) {
        #pragma unroll
        for (int i = 0; i < 4; i++) {
            const int idx = i * 256 + tid;
            const int ar = idx >> 3, ac4 = (idx & 7) * 4;
            pa[i] = *(const float4*)(Ab + (size_t)ar * lda + k0 + ac4);
            const int br = idx >> 5, bc4 = (idx & 31) * 4;
            pb[i] = *(const float4*)(Bb + (size_t)(k0 + br) * ldb + bc4);
        }
    };
    auto store_smem = [&](int buf, const float4* pa, const float4* pb) {
        #pragma unroll
        for (int i = 0; i < 4; i++) {
            const int idx = i * 256 + tid;
            const int ar = idx >> 3, ac4 = (idx & 7) * 4;
            uint4 ua; ua.x = tf32r(pa[i].x); ua.y = tf32r(pa[i].y);
                      ua.z = tf32r(pa[i].z); ua.w = tf32r(pa[i].w);
            *(uint4*)(As[buf] + ar * ALD + ac4) = ua;
            const int br = idx >> 5, bc4 = (idx & 31) * 4;
            uint4 ub; ub.x = tf32r(pb[i].x); ub.y = tf32r(pb[i].y);
                      ub.z = tf32r(pb[i].z); ub.w = tf32r(pb[i].w);
            *(uint4*)(Bs[buf] + br * BLD + bc4) = ub;
        }
    };

    // prologue: tile 0
    {
        float4 pa[4], pb[4];
        load_regs(0, pa, pb);
        store_smem(0, pa, pb);
    }
    __syncthreads();

    const int nch = K >> 5;
    for (int ch = 0; ch < nch; ch++) {
        const int buf = ch & 1;

        float4 pa[4], pb[4];
        if (ch + 1 < nch) load_regs((ch + 1) * 32, pa, pb);

        const uint32_t* Asb = (const uint32_t*)As[buf];
        const uint32_t* Bsb = (const uint32_t*)Bs[buf];

        #pragma unroll
        for (int ks = 0; ks < 4; ks++) {
            const int k0 = ks * 8;
            uint32_t af[4][4], bf[4][2];
            #pragma unroll
            for (int i = 0; i < 4; i++) {
                const int r0 = wrow + i * 16 + g;
                af[i][0] = Asb[(r0    ) * ALD + k0 + t];
                af[i][1] = Asb[(r0 + 8) * ALD + k0 + t];
                af[i][2] = Asb[(r0    ) * ALD + k0 + t + 4];
                af[i][3] = Asb[(r0 + 8) * ALD + k0 + t + 4];
            }
            #pragma unroll
            for (int j = 0; j < 4; j++) {
                const int c = wcol + j * 8 + g;
                bf[j][0] = Bsb[(k0 + t    ) * BLD + c];
                bf[j][1] = Bsb[(k0 + t + 4) * BLD + c];
            }
            #pragma unroll
            for (int i = 0; i < 4; i++)
                #pragma unroll
                for (int j = 0; j < 4; j++)
                    mma_tf32(acc[i][j], af[i], bf[j]);
        }

        __syncthreads();
        if (ch + 1 < nch) {
            store_smem(buf ^ 1, pa, pb);
            __syncthreads();
        }
    }

    // epilogue: c0/c1 -> (row, 2t), c2/c3 -> (row+8, 2t)
    #pragma unroll
    for (int i = 0; i < 4; i++) {
        const int r0 = brow + wrow + i * 16 + g;
        #pragma unroll
        for (int j = 0; j < 4; j++) {
            const int c = bcol + wcol + j * 8 + 2 * t;
            float b0 = 0.f, b1 = 0.f;
            if (bias) { b0 = bias[c]; b1 = bias[c + 1]; }
            float2 v0 = { acc[i][j][0] + b0, acc[i][j][1] + b1 };
            float2 v1 = { acc[i][j][2] + b0, acc[i][j][3] + b1 };
            *(float2*)(C + (size_t)r0 * ldc + c)       = v0;
            *(float2*)(C + (size_t)(r0 + 8) * ldc + c) = v1;
        }
    }
}

// ===========================================================================
// Flash-style attention, fp32 (round-6 tensorization target)
// ===========================================================================
__global__ __launch_bounds__(64) void attn_kernel(
    const float* __restrict__ Q, const float* __restrict__ KV,
    float* __restrict__ O)
{
    const int qt = blockIdx.x;
    const int h  = blockIdx.y;
    const int b  = blockIdx.z;
    const int t  = threadIdx.x;

    __shared__ float Ks[32][64];
    __shared__ float Vs[32][64];

    const float scale = 0.125f;

    float q[64];
    {
        const float* qrow = Q + ((size_t)b * SQ + qt * 64 + t) * INNER + h * DHEAD;
        #pragma unroll
        for (int d = 0; d < 64; d += 4) {
            float4 v = *(const float4*)(qrow + d);
            q[d + 0] = v.x; q[d + 1] = v.y; q[d + 2] = v.z; q[d + 3] = v.w;
        }
    }

    float m = -INFINITY, l = 0.f;
    float o[64];
    #pragma unroll
    for (int d = 0; d < 64; d++) o[d] = 0.f;

    for (int kv0 = 0; kv0 < SKV; kv0 += 32) {
        __syncthreads();
        for (int i = t; i < 32 * 16; i += 64) {
            const int j  = i >> 4;
            const int d4 = i & 15;
            const size_t base = ((size_t)b * SKV + kv0 + j) * (2 * INNER) + h * DHEAD;
            ((float4*)Ks[j])[d4] = *(const float4*)(KV + base + d4 * 4);
            ((float4*)Vs[j])[d4] = *(const float4*)(KV + base + INNER + d4 * 4);
        }
        __syncthreads();

        float s[32];
        float tmax = -INFINITY;
        #pragma unroll
        for (int j = 0; j < 32; j++) {
            float acc = 0.f;
            #pragma unroll
            for (int d = 0; d < 64; d++) acc += q[d] * Ks[j][d];
            s[j] = acc * scale;
            tmax = fmaxf(tmax, s[j]);
        }

        const float mnew = fmaxf(m, tmax);
        const float c = __expf(m - mnew);
        l *= c;
        #pragma unroll
        for (int d = 0; d < 64; d++) o[d] *= c;
        m = mnew;

        #pragma unroll
        for (int j = 0; j < 32; j++) {
            const float p = __expf(s[j] - m);
            l += p;
            #pragma unroll
            for (int d = 0; d < 64; d++) o[d] += p * Vs[j][d];
        }
    }

    const float inv = 1.f / l;
    float* orow = O + ((size_t)b * SQ + qt * 64 + t) * INNER + h * DHEAD;
    #pragma unroll
    for (int d = 0; d < 64; d += 4) {
        float4 v;
        v.x = o[d + 0] * inv; v.y = o[d + 1] * inv;
        v.z = o[d + 2] * inv; v.w = o[d + 3] * inv;
        *(float4*)(orow + d) = v;
    }
}

// ===========================================================================
// kernel_launch
// ===========================================================================
extern "C" void kernel_launch(void* const* d_in, const int* in_sizes, int n_in,
                              void* d_out, int out_size)
{
    const float* x_q   = (const float*)d_in[0];
    const float* x_kv  = (const float*)d_in[1];
    const float* W_qkv = (const float*)d_in[2];  // [1024, 3072]
    const float* W_out = (const float*)d_in[3];  // [1024, 1024]
    const float* b_out = (const float*)d_in[4];  // [1024]
    float* out = (float*)d_out;

    float *q, *kv, *o;
    cudaGetSymbolAddress((void**)&q,  g_q);
    cudaGetSymbolAddress((void**)&kv, g_kv);
    cudaGetSymbolAddress((void**)&o,  g_o);

    cudaFuncSetAttribute(gemm_tf32mma,
                         cudaFuncAttributeMaxDynamicSharedMemorySize, SM_BYTES);

    // Q = x_q @ W_qkv[:, 0:1024]             -> [4096, 1024]
    gemm_tf32mma<<<dim3(INNER / 128, MQ / 128), 256, SM_BYTES>>>(
        x_q, W_qkv, q, nullptr, DIM, DIM, 3 * INNER, INNER);

    // KV = x_kv @ W_qkv[:, 1024:3072]        -> [4096, 2048]  (K | V)
    gemm_tf32mma<<<dim3(2 * INNER / 128, MKV / 128), 256, SM_BYTES>>>(
        x_kv, W_qkv + INNER, kv, nullptr, DIM, DIM, 3 * INNER, 2 * INNER);

    // attention                               -> O [4096, 1024]
    attn_kernel<<<dim3(SQ / 64, HEADS, BATCH), 64>>>(q, kv, o);

    // out = O @ W_out + b_out                 -> [4096, 1024]
    gemm_tf32mma<<<dim3(DIM / 128, MQ / 128), 256, SM_BYTES>>>(
        o, W_out, out, b_out, INNER, INNER, DIM, DIM);
}

// round 7
// speedup vs baseline: 2.0141x; 1.5565x over previous
#include <cuda_runtime.h>
#include <cstdint>
#include <math.h>

// Problem constants (fixed by the dataset)
#define BATCH   2
#define SQ      2048
#define SKV     2048
#define DIM     1024
#define HEADS   16
#define DHEAD   64
#define INNER   1024            // HEADS * DIM_HEAD
#define MQ      (BATCH * SQ)    // 4096
#define MKV     (BATCH * SKV)   // 4096

// Scratch (no cudaMalloc allowed)
__device__ float g_q  [MQ  * INNER];          // 16 MB
__device__ float g_kv [MKV * 2 * INNER];      // 32 MB (K | V)
__device__ float g_o  [MQ  * INNER];          // 16 MB

// fp32 -> tf32 (round-to-nearest) as raw bits
__device__ __forceinline__ uint32_t tf32r(float x) {
    uint32_t r;
    asm("cvt.rna.tf32.f32 %0, %1;" : "=r"(r) : "f"(x));
    return r;
}

// warp-level tf32 MMA: D[16x8] += A[16x8] * B[8x8]  (row.col)
__device__ __forceinline__ void mma_tf32(float* d, const uint32_t* a, const uint32_t* b) {
    asm volatile(
        "mma.sync.aligned.m16n8k8.row.col.f32.tf32.tf32.f32 "
        "{%0,%1,%2,%3}, {%4,%5,%6,%7}, {%8,%9}, {%0,%1,%2,%3};"
        : "+f"(d[0]), "+f"(d[1]), "+f"(d[2]), "+f"(d[3])
        : "r"(a[0]), "r"(a[1]), "r"(a[2]), "r"(a[3]), "r"(b[0]), "r"(b[1]));
}

// ===========================================================================
// tf32 tensor-core GEMM: C[M,N] = A[M,K] @ B[K,N] (+ bias)   (unchanged, WIN)
// ===========================================================================
#define ALD 36
#define BLD 136
#define A_TILE_F (128 * ALD)
#define B_TILE_F (32 * BLD)
#define SM_FLOATS (2 * (A_TILE_F + B_TILE_F))
#define SM_BYTES  (SM_FLOATS * 4)   // 71680

__global__ __launch_bounds__(256) void gemm_tf32mma(
    const float* __restrict__ A, const float* __restrict__ B,
    float* __restrict__ C, const float* __restrict__ bias,
    int K, int lda, int ldb, int ldc)
{
    extern __shared__ float smem[];
    float* As[2] = { smem,                         smem + A_TILE_F + B_TILE_F };
    float* Bs[2] = { smem + A_TILE_F,              smem + 2 * A_TILE_F + B_TILE_F };

    const int tid  = threadIdx.x;
    const int wid  = tid >> 5;
    const int lane = tid & 31;
    const int g    = lane >> 2;
    const int t    = lane & 3;
    const int wrow = (wid & 1) * 64;
    const int wcol = (wid >> 1) * 32;

    const int brow = blockIdx.y * 128;
    const int bcol = blockIdx.x * 128;

    float acc[4][4][4];
    #pragma unroll
    for (int i = 0; i < 4; i++)
        #pragma unroll
        for (int j = 0; j < 4; j++)
            #pragma unroll
            for (int r = 0; r < 4; r++) acc[i][j][r] = 0.f;

    const float* Ab = A + (size_t)brow * lda;
    const float* Bb = B + bcol;

    auto load_regs = [&](int k0, float4* pa, float4* pb) {
        #pragma unroll
        for (int i = 0; i < 4; i++) {
            const int idx = i * 256 + tid;
            const int ar = idx >> 3, ac4 = (idx & 7) * 4;
            pa[i] = *(const float4*)(Ab + (size_t)ar * lda + k0 + ac4);
            const int br = idx >> 5, bc4 = (idx & 31) * 4;
            pb[i] = *(const float4*)(Bb + (size_t)(k0 + br) * ldb + bc4);
        }
    };
    auto store_smem = [&](int buf, const float4* pa, const float4* pb) {
        #pragma unroll
        for (int i = 0; i < 4; i++) {
            const int idx = i * 256 + tid;
            const int ar = idx >> 3, ac4 = (idx & 7) * 4;
            uint4 ua; ua.x = tf32r(pa[i].x); ua.y = tf32r(pa[i].y);
                      ua.z = tf32r(pa[i].z); ua.w = tf32r(pa[i].w);
            *(uint4*)(As[buf] + ar * ALD + ac4) = ua;
            const int br = idx >> 5, bc4 = (idx & 31) * 4;
            uint4 ub; ub.x = tf32r(pb[i].x); ub.y = tf32r(pb[i].y);
                      ub.z = tf32r(pb[i].z); ub.w = tf32r(pb[i].w);
            *(uint4*)(Bs[buf] + br * BLD + bc4) = ub;
        }
    };

    {
        float4 pa[4], pb[4];
        load_regs(0, pa, pb);
        store_smem(0, pa, pb);
    }
    __syncthreads();

    const int nch = K >> 5;
    for (int ch = 0; ch < nch; ch++) {
        const int buf = ch & 1;

        float4 pa[4], pb[4];
        if (ch + 1 < nch) load_regs((ch + 1) * 32, pa, pb);

        const uint32_t* Asb = (const uint32_t*)As[buf];
        const uint32_t* Bsb = (const uint32_t*)Bs[buf];

        #pragma unroll
        for (int ks = 0; ks < 4; ks++) {
            const int k0 = ks * 8;
            uint32_t af[4][4], bf[4][2];
            #pragma unroll
            for (int i = 0; i < 4; i++) {
                const int r0 = wrow + i * 16 + g;
                af[i][0] = Asb[(r0    ) * ALD + k0 + t];
                af[i][1] = Asb[(r0 + 8) * ALD + k0 + t];
                af[i][2] = Asb[(r0    ) * ALD + k0 + t + 4];
                af[i][3] = Asb[(r0 + 8) * ALD + k0 + t + 4];
            }
            #pragma unroll
            for (int j = 0; j < 4; j++) {
                const int c = wcol + j * 8 + g;
                bf[j][0] = Bsb[(k0 + t    ) * BLD + c];
                bf[j][1] = Bsb[(k0 + t + 4) * BLD + c];
            }
            #pragma unroll
            for (int i = 0; i < 4; i++)
                #pragma unroll
                for (int j = 0; j < 4; j++)
                    mma_tf32(acc[i][j], af[i], bf[j]);
        }

        __syncthreads();
        if (ch + 1 < nch) {
            store_smem(buf ^ 1, pa, pb);
            __syncthreads();
        }
    }

    #pragma unroll
    for (int i = 0; i < 4; i++) {
        const int r0 = brow + wrow + i * 16 + g;
        #pragma unroll
        for (int j = 0; j < 4; j++) {
            const int c = bcol + wcol + j * 8 + 2 * t;
            float b0 = 0.f, b1 = 0.f;
            if (bias) { b0 = bias[c]; b1 = bias[c + 1]; }
            float2 v0 = { acc[i][j][0] + b0, acc[i][j][1] + b1 };
            float2 v1 = { acc[i][j][2] + b0, acc[i][j][3] + b1 };
            *(float2*)(C + (size_t)r0 * ldc + c)       = v0;
            *(float2*)(C + (size_t)(r0 + 8) * ldc + c) = v1;
        }
    }
}

// ===========================================================================
// Tensor-core flash attention (tf32 mma.sync).
// CTA: 128 q-rows x (b,h). 8 warps x 16 rows. KV tiles of 64.
// K smem [kv][68] (B-frag reads bank 4g+t), V smem [kv][72] (banks 8t+g),
// per-warp P smem [16][68] for C->A fragment layout conversion.
// ===========================================================================
#define KPAD 68
#define VPAD 72
#define PPAD 68
#define ATT_KS_F   (64 * KPAD)                 // 4352
#define ATT_VS_F   (64 * VPAD)                 // 4608
#define ATT_PS_F   (8 * 16 * PPAD)             // 8704
#define ATT_SM_F   (ATT_KS_F + ATT_VS_F + ATT_PS_F)
#define ATT_SM_BYTES (ATT_SM_F * 4)            // 70656

__global__ __launch_bounds__(256) void attn_tc(
    const float* __restrict__ Q, const float* __restrict__ KV,
    float* __restrict__ O)
{
    extern __shared__ float asm_[];
    float* Ksm = asm_;
    float* Vsm = asm_ + ATT_KS_F;
    float* Psm = asm_ + ATT_KS_F + ATT_VS_F;
    uint32_t* Ksb = (uint32_t*)Ksm;
    uint32_t* Vsb = (uint32_t*)Vsm;
    uint32_t* Psb = (uint32_t*)Psm;

    const int tid  = threadIdx.x;
    const int wid  = tid >> 5;
    const int lane = tid & 31;
    const int g    = lane >> 2;     // 0..7
    const int t    = lane & 3;      // 0..3

    const int qt = blockIdx.x;      // q tile (128 rows)
    const int h  = blockIdx.y;
    const int b  = blockIdx.z;

    const int wrow   = wid * 16;                    // warp's rows in q tile
    const int qrow0  = qt * 128 + wrow + g;         // this thread's row (and +8)
    const size_t qg0 = ((size_t)b * SQ + qrow0) * INNER + h * DHEAD;

    // ---- Q fragments (permanent): qa[ks] = {A[g][t+8ks], A[g+8][..], A[g][t+4+8ks], A[g+8][..]}
    // scale 1/8 folded in before tf32 rounding (exact power of two).
    uint32_t qa[8][4];
    {
        const float* q0 = Q + qg0;
        const float* q1 = q0 + 8 * INNER;
        #pragma unroll
        for (int ks = 0; ks < 8; ks++) {
            qa[ks][0] = tf32r(0.125f * q0[8 * ks + t]);
            qa[ks][1] = tf32r(0.125f * q1[8 * ks + t]);
            qa[ks][2] = tf32r(0.125f * q0[8 * ks + t + 4]);
            qa[ks][3] = tf32r(0.125f * q1[8 * ks + t + 4]);
        }
    }

    float m0 = -INFINITY, m1 = -INFINITY;
    float l0 = 0.f, l1 = 0.f;
    float o[8][4];
    #pragma unroll
    for (int j = 0; j < 8; j++)
        #pragma unroll
        for (int r = 0; r < 4; r++) o[j][r] = 0.f;

    const int pbase = wid * 16 * PPAD;

    for (int kv0 = 0; kv0 < SKV; kv0 += 64) {
        __syncthreads();
        // ---- load K,V tile (64 x 64 each), tf32-rounded
        #pragma unroll
        for (int i = 0; i < 4; i++) {
            const int idx = i * 256 + tid;
            const int j   = idx >> 4;
            const int d4  = (idx & 15) * 4;
            const float* kp = KV + ((size_t)b * SKV + kv0 + j) * (2 * INNER)
                                 + h * DHEAD + d4;
            float4 kv4 = *(const float4*)kp;
            uint4 uk; uk.x = tf32r(kv4.x); uk.y = tf32r(kv4.y);
                      uk.z = tf32r(kv4.z); uk.w = tf32r(kv4.w);
            *(uint4*)(Ksb + j * KPAD + d4) = uk;
            float4 vv4 = *(const float4*)(kp + INNER);
            uint4 uv; uv.x = tf32r(vv4.x); uv.y = tf32r(vv4.y);
                      uv.z = tf32r(vv4.z); uv.w = tf32r(vv4.w);
            *(uint4*)(Vsb + j * VPAD + d4) = uv;
        }
        __syncthreads();

        // ---- S = Q @ K^T : B(k=d, n=kv) = K[kv][d] => b0 = Ks[n*KPAD + k0+t]
        float s[8][4];
        #pragma unroll
        for (int j = 0; j < 8; j++)
            #pragma unroll
            for (int r = 0; r < 4; r++) s[j][r] = 0.f;

        #pragma unroll
        for (int ks = 0; ks < 8; ks++) {
            const int k0 = ks * 8;
            uint32_t bf[8][2];
            #pragma unroll
            for (int j = 0; j < 8; j++) {
                const int n = j * 8 + g;
                bf[j][0] = Ksb[n * KPAD + k0 + t];
                bf[j][1] = Ksb[n * KPAD + k0 + t + 4];
            }
            #pragma unroll
            for (int j = 0; j < 8; j++)
                mma_tf32(s[j], qa[ks], bf[j]);
        }

        // ---- online softmax on fragments (rows g and g+8)
        float tm0 = -INFINITY, tm1 = -INFINITY;
        #pragma unroll
        for (int j = 0; j < 8; j++) {
            tm0 = fmaxf(tm0, fmaxf(s[j][0], s[j][1]));
            tm1 = fmaxf(tm1, fmaxf(s[j][2], s[j][3]));
        }
        tm0 = fmaxf(tm0, __shfl_xor_sync(0xffffffffu, tm0, 1));
        tm0 = fmaxf(tm0, __shfl_xor_sync(0xffffffffu, tm0, 2));
        tm1 = fmaxf(tm1, __shfl_xor_sync(0xffffffffu, tm1, 1));
        tm1 = fmaxf(tm1, __shfl_xor_sync(0xffffffffu, tm1, 2));

        const float m0n = fmaxf(m0, tm0);
        const float m1n = fmaxf(m1, tm1);
        const float a0 = __expf(m0 - m0n);
        const float a1 = __expf(m1 - m1n);
        l0 *= a0; l1 *= a1;
        #pragma unroll
        for (int j = 0; j < 8; j++) {
            o[j][0] *= a0; o[j][1] *= a0;
            o[j][2] *= a1; o[j][3] *= a1;
        }
        m0 = m0n; m1 = m1n;

        float rs0 = 0.f, rs1 = 0.f;
        #pragma unroll
        for (int j = 0; j < 8; j++) {
            const float p0 = __expf(s[j][0] - m0);
            const float p1 = __expf(s[j][1] - m0);
            const float p2 = __expf(s[j][2] - m1);
            const float p3 = __expf(s[j][3] - m1);
            rs0 += p0 + p1;
            rs1 += p2 + p3;
            const int c = j * 8 + 2 * t;
            Psb[pbase + g * PPAD + c]           = tf32r(p0);
            Psb[pbase + g * PPAD + c + 1]       = tf32r(p1);
            Psb[pbase + (g + 8) * PPAD + c]     = tf32r(p2);
            Psb[pbase + (g + 8) * PPAD + c + 1] = tf32r(p3);
        }
        rs0 += __shfl_xor_sync(0xffffffffu, rs0, 1);
        rs0 += __shfl_xor_sync(0xffffffffu, rs0, 2);
        rs1 += __shfl_xor_sync(0xffffffffu, rs1, 1);
        rs1 += __shfl_xor_sync(0xffffffffu, rs1, 2);
        l0 += rs0; l1 += rs1;

        __syncwarp();

        // ---- O += P @ V : A = P[16 x 64] from Psm, B(k=kv, n=d) = V[kv][d]
        #pragma unroll
        for (int ks = 0; ks < 8; ks++) {
            const int k0 = ks * 8;
            uint32_t pa[4];
            pa[0] = Psb[pbase + g * PPAD + k0 + t];
            pa[1] = Psb[pbase + (g + 8) * PPAD + k0 + t];
            pa[2] = Psb[pbase + g * PPAD + k0 + t + 4];
            pa[3] = Psb[pbase + (g + 8) * PPAD + k0 + t + 4];
            uint32_t bf[8][2];
            #pragma unroll
            for (int j = 0; j < 8; j++) {
                const int n = j * 8 + g;
                bf[j][0] = Vsb[(k0 + t    ) * VPAD + n];
                bf[j][1] = Vsb[(k0 + t + 4) * VPAD + n];
            }
            #pragma unroll
            for (int j = 0; j < 8; j++)
                mma_tf32(o[j], pa, bf[j]);
        }
        __syncwarp();   // P smem reuse next iteration
    }

    // ---- epilogue
    const float inv0 = 1.f / l0;
    const float inv1 = 1.f / l1;
    float* o0 = O + qg0;
    float* o1 = o0 + 8 * INNER;
    #pragma unroll
    for (int j = 0; j < 8; j++) {
        const int c = j * 8 + 2 * t;
        float2 v0 = { o[j][0] * inv0, o[j][1] * inv0 };
        float2 v1 = { o[j][2] * inv1, o[j][3] * inv1 };
        *(float2*)(o0 + c) = v0;
        *(float2*)(o1 + c) = v1;
    }
}

// ===========================================================================
// kernel_launch
// ===========================================================================
extern "C" void kernel_launch(void* const* d_in, const int* in_sizes, int n_in,
                              void* d_out, int out_size)
{
    const float* x_q   = (const float*)d_in[0];
    const float* x_kv  = (const float*)d_in[1];
    const float* W_qkv = (const float*)d_in[2];  // [1024, 3072]
    const float* W_out = (const float*)d_in[3];  // [1024, 1024]
    const float* b_out = (const float*)d_in[4];  // [1024]
    float* out = (float*)d_out;

    float *q, *kv, *o;
    cudaGetSymbolAddress((void**)&q,  g_q);
    cudaGetSymbolAddress((void**)&kv, g_kv);
    cudaGetSymbolAddress((void**)&o,  g_o);

    cudaFuncSetAttribute(gemm_tf32mma,
                         cudaFuncAttributeMaxDynamicSharedMemorySize, SM_BYTES);
    cudaFuncSetAttribute(attn_tc,
                         cudaFuncAttributeMaxDynamicSharedMemorySize, ATT_SM_BYTES);

    // Q = x_q @ W_qkv[:, 0:1024]             -> [4096, 1024]
    gemm_tf32mma<<<dim3(INNER / 128, MQ / 128), 256, SM_BYTES>>>(
        x_q, W_qkv, q, nullptr, DIM, DIM, 3 * INNER, INNER);

    // KV = x_kv @ W_qkv[:, 1024:3072]        -> [4096, 2048]  (K | V)
    gemm_tf32mma<<<dim3(2 * INNER / 128, MKV / 128), 256, SM_BYTES>>>(
        x_kv, W_qkv + INNER, kv, nullptr, DIM, DIM, 3 * INNER, 2 * INNER);

    // attention (tensor core)                 -> O [4096, 1024]
    attn_tc<<<dim3(SQ / 128, HEADS, BATCH), 256, ATT_SM_BYTES>>>(q, kv, o);

    // out = O @ W_out + b_out                 -> [4096, 1024]
    gemm_tf32mma<<<dim3(DIM / 128, MQ / 128), 256, SM_BYTES>>>(
        o, W_out, out, b_out, INNER, INNER, DIM, DIM);
}

// round 8
// speedup vs baseline: 2.9062x; 1.4429x over previous
#include <cuda_runtime.h>
#include <cstdint>
#include <math.h>

// Problem constants (fixed by the dataset)
#define BATCH   2
#define SQ      2048
#define SKV     2048
#define DIM     1024
#define HEADS   16
#define DHEAD   64
#define INNER   1024            // HEADS * DIM_HEAD
#define MQ      (BATCH * SQ)    // 4096
#define MKV     (BATCH * SKV)   // 4096

// Scratch (no cudaMalloc allowed)
__device__ float g_q  [MQ  * INNER];          // 16 MB
__device__ float g_kv [MKV * 2 * INNER];      // 32 MB (K | V)
__device__ float g_o  [MQ  * INNER];          // 16 MB

// fp32 -> tf32 (round-to-nearest) as raw bits
__device__ __forceinline__ uint32_t tf32r(float x) {
    uint32_t r;
    asm("cvt.rna.tf32.f32 %0, %1;" : "=r"(r) : "f"(x));
    return r;
}

// warp-level tf32 MMA: D[16x8] += A[16x8] * B[8x8]  (row.col)
__device__ __forceinline__ void mma_tf32(float* d, const uint32_t* a, const uint32_t* b) {
    asm volatile(
        "mma.sync.aligned.m16n8k8.row.col.f32.tf32.tf32.f32 "
        "{%0,%1,%2,%3}, {%4,%5,%6,%7}, {%8,%9}, {%0,%1,%2,%3};"
        : "+f"(d[0]), "+f"(d[1]), "+f"(d[2]), "+f"(d[3])
        : "r"(a[0]), "r"(a[1]), "r"(a[2]), "r"(a[3]), "r"(b[0]), "r"(b[1]));
}

// ===========================================================================
// tf32 tensor-core GEMM: C[M,N] = A[M,K] @ B[K,N] (+ bias)
// 128x128 CTA tile, K-tile 32, double buffer, ONE sync per chunk.
// ===========================================================================
#define ALD 36
#define BLD 136
#define A_TILE_F (128 * ALD)
#define B_TILE_F (32 * BLD)
#define SM_FLOATS (2 * (A_TILE_F + B_TILE_F))
#define SM_BYTES  (SM_FLOATS * 4)   // 71680

__global__ __launch_bounds__(256) void gemm_tf32mma(
    const float* __restrict__ A, const float* __restrict__ B,
    float* __restrict__ C, const float* __restrict__ bias,
    int K, int lda, int ldb, int ldc)
{
    extern __shared__ float smem[];
    float* As[2] = { smem,            smem + A_TILE_F + B_TILE_F };
    float* Bs[2] = { smem + A_TILE_F, smem + 2 * A_TILE_F + B_TILE_F };

    const int tid  = threadIdx.x;
    const int wid  = tid >> 5;
    const int lane = tid & 31;
    const int g    = lane >> 2;
    const int t    = lane & 3;
    const int wrow = (wid & 1) * 64;
    const int wcol = (wid >> 1) * 32;

    const int brow = blockIdx.y * 128;
    const int bcol = blockIdx.x * 128;

    float acc[4][4][4];
    #pragma unroll
    for (int i = 0; i < 4; i++)
        #pragma unroll
        for (int j = 0; j < 4; j++)
            #pragma unroll
            for (int r = 0; r < 4; r++) acc[i][j][r] = 0.f;

    const float* Ab = A + (size_t)brow * lda;
    const float* Bb = B + bcol;

    auto load_regs = [&](int k0, float4* pa, float4* pb) {
        #pragma unroll
        for (int i = 0; i < 4; i++) {
            const int idx = i * 256 + tid;
            const int ar = idx >> 3, ac4 = (idx & 7) * 4;
            pa[i] = *(const float4*)(Ab + (size_t)ar * lda + k0 + ac4);
            const int br = idx >> 5, bc4 = (idx & 31) * 4;
            pb[i] = *(const float4*)(Bb + (size_t)(k0 + br) * ldb + bc4);
        }
    };
    auto store_smem = [&](int buf, const float4* pa, const float4* pb) {
        #pragma unroll
        for (int i = 0; i < 4; i++) {
            const int idx = i * 256 + tid;
            const int ar = idx >> 3, ac4 = (idx & 7) * 4;
            uint4 ua; ua.x = tf32r(pa[i].x); ua.y = tf32r(pa[i].y);
                      ua.z = tf32r(pa[i].z); ua.w = tf32r(pa[i].w);
            *(uint4*)(As[buf] + ar * ALD + ac4) = ua;
            const int br = idx >> 5, bc4 = (idx & 31) * 4;
            uint4 ub; ub.x = tf32r(pb[i].x); ub.y = tf32r(pb[i].y);
                      ub.z = tf32r(pb[i].z); ub.w = tf32r(pb[i].w);
            *(uint4*)(Bs[buf] + br * BLD + bc4) = ub;
        }
    };

    {
        float4 pa[4], pb[4];
        load_regs(0, pa, pb);
        store_smem(0, pa, pb);
    }
    __syncthreads();

    const int nch = K >> 5;
    for (int ch = 0; ch < nch; ch++) {
        const int buf = ch & 1;

        float4 pa[4], pb[4];
        if (ch + 1 < nch) load_regs((ch + 1) * 32, pa, pb);

        const uint32_t* Asb = (const uint32_t*)As[buf];
        const uint32_t* Bsb = (const uint32_t*)Bs[buf];

        #pragma unroll
        for (int ks = 0; ks < 4; ks++) {
            const int k0 = ks * 8;
            uint32_t af[4][4], bf[4][2];
            #pragma unroll
            for (int i = 0; i < 4; i++) {
                const int r0 = wrow + i * 16 + g;
                af[i][0] = Asb[(r0    ) * ALD + k0 + t];
                af[i][1] = Asb[(r0 + 8) * ALD + k0 + t];
                af[i][2] = Asb[(r0    ) * ALD + k0 + t + 4];
                af[i][3] = Asb[(r0 + 8) * ALD + k0 + t + 4];
            }
            #pragma unroll
            for (int j = 0; j < 4; j++) {
                const int c = wcol + j * 8 + g;
                bf[j][0] = Bsb[(k0 + t    ) * BLD + c];
                bf[j][1] = Bsb[(k0 + t + 4) * BLD + c];
            }
            #pragma unroll
            for (int i = 0; i < 4; i++)
                #pragma unroll
                for (int j = 0; j < 4; j++)
                    mma_tf32(acc[i][j], af[i], bf[j]);
        }

        // Write next tile into the other buffer (no warp can still be reading
        // it: its readers finished before the previous __syncthreads), then
        // a single barrier publishes it for the next iteration.
        if (ch + 1 < nch) store_smem(buf ^ 1, pa, pb);
        __syncthreads();
    }

    #pragma unroll
    for (int i = 0; i < 4; i++) {
        const int r0 = brow + wrow + i * 16 + g;
        #pragma unroll
        for (int j = 0; j < 4; j++) {
            const int c = bcol + wcol + j * 8 + 2 * t;
            float b0 = 0.f, b1 = 0.f;
            if (bias) { b0 = bias[c]; b1 = bias[c + 1]; }
            float2 v0 = { acc[i][j][0] + b0, acc[i][j][1] + b1 };
            float2 v1 = { acc[i][j][2] + b0, acc[i][j][3] + b1 };
            *(float2*)(C + (size_t)r0 * ldc + c)       = v0;
            *(float2*)(C + (size_t)(r0 + 8) * ldc + c) = v1;
        }
    }
}

// ===========================================================================
// Tensor-core flash attention v2 (tf32 mma.sync).
// CTA: 256 q-rows x (b,h), 512 threads = 16 warps x 16 rows.
// KV tiles of 32 rows, double-buffered smem + register prefetch,
// ONE __syncthreads per tile. Warp-uniform running max (numerically exact
// after l-normalization) -> uniform skip of the o-rescale.
// ===========================================================================
#define KT    32                    // kv rows per tile
#define KPAD  68                    // K smem pitch: frag reads hit bank 4g+t
#define VPAD  72                    // V smem pitch: frag reads hit bank 8t+g
#define PPAD  36                    // P smem pitch: frag reads hit bank 4g+t
#define KS_F  (KT * KPAD)           // 2176
#define VS_F  (KT * VPAD)           // 2304
#define BUF_F (KS_F + VS_F)         // 4480 per stage
#define PS_F  (16 * 16 * PPAD)      // 9216 (16 warps)
#define ATT_SM_F     (2 * BUF_F + PS_F)
#define ATT_SM_BYTES (ATT_SM_F * 4) // 72704

__global__ __launch_bounds__(512) void attn_tc(
    const float* __restrict__ Q, const float* __restrict__ KV,
    float* __restrict__ O)
{
    extern __shared__ float asm_[];
    uint32_t* Pb = (uint32_t*)(asm_ + 2 * BUF_F);

    const int tid  = threadIdx.x;
    const int wid  = tid >> 5;      // 0..15
    const int lane = tid & 31;
    const int g    = lane >> 2;     // 0..7
    const int t    = lane & 3;      // 0..3

    const int qt = blockIdx.x;      // q tile (256 rows)
    const int h  = blockIdx.y;
    const int b  = blockIdx.z;

    const int qrow0  = qt * 256 + wid * 16 + g;
    const size_t qg0 = ((size_t)b * SQ + qrow0) * INNER + h * DHEAD;

    // Q fragments (permanent), scale 1/8 folded in pre-rounding (exact pow2)
    uint32_t qa[8][4];
    {
        const float* q0 = Q + qg0;
        const float* q1 = q0 + 8 * INNER;
        #pragma unroll
        for (int ks = 0; ks < 8; ks++) {
            qa[ks][0] = tf32r(0.125f * q0[8 * ks + t]);
            qa[ks][1] = tf32r(0.125f * q1[8 * ks + t]);
            qa[ks][2] = tf32r(0.125f * q0[8 * ks + t + 4]);
            qa[ks][3] = tf32r(0.125f * q1[8 * ks + t + 4]);
        }
    }

    float m = -INFINITY;            // warp-uniform running max
    float l0 = 0.f, l1 = 0.f;       // per-row sums (rows g, g+8)
    float o[8][4];
    #pragma unroll
    for (int j = 0; j < 8; j++)
        #pragma unroll
        for (int r = 0; r < 4; r++) o[j][r] = 0.f;

    const int pbase = wid * 16 * PPAD;

    // tile load/store: 512 threads, one float4 of K and V each
    const int ldj  = tid >> 4;          // kv row 0..31
    const int ldd4 = (tid & 15) * 4;    // d offset
    auto ldtile = [&](int n, float4& kr, float4& vr) {
        const float* p = KV + ((size_t)b * SKV + n * KT + ldj) * (2 * INNER)
                            + h * DHEAD + ldd4;
        kr = *(const float4*)p;
        vr = *(const float4*)(p + INNER);
    };
    auto sttile = [&](int buf, const float4& kr, const float4& vr) {
        uint32_t* kb = (uint32_t*)(asm_ + buf * BUF_F);
        uint32_t* vb = kb + KS_F;
        uint4 uk; uk.x = tf32r(kr.x); uk.y = tf32r(kr.y);
                  uk.z = tf32r(kr.z); uk.w = tf32r(kr.w);
        *(uint4*)(kb + ldj * KPAD + ldd4) = uk;
        uint4 uv; uv.x = tf32r(vr.x); uv.y = tf32r(vr.y);
                  uv.z = tf32r(vr.z); uv.w = tf32r(vr.w);
        *(uint4*)(vb + ldj * VPAD + ldd4) = uv;
    };

    {
        float4 kr, vr;
        ldtile(0, kr, vr);
        sttile(0, kr, vr);
    }
    __syncthreads();

    const int NT = SKV / KT;   // 64
    for (int n = 0; n < NT; n++) {
        const int buf = n & 1;

        float4 krn, vrn;
        if (n + 1 < NT) ldtile(n + 1, krn, vrn);   // prefetch (latency hidden)

        const uint32_t* Ksb = (const uint32_t*)(asm_ + buf * BUF_F);
        const uint32_t* Vsb = Ksb + KS_F;

        // ---- S[16x32] = Q @ K^T
        float s[4][4];
        #pragma unroll
        for (int j = 0; j < 4; j++)
            #pragma unroll
            for (int r = 0; r < 4; r++) s[j][r] = 0.f;

        #pragma unroll
        for (int ks = 0; ks < 8; ks++) {
            const int k0 = ks * 8;
            uint32_t bf[4][2];
            #pragma unroll
            for (int j = 0; j < 4; j++) {
                const int nn = j * 8 + g;
                bf[j][0] = Ksb[nn * KPAD + k0 + t];
                bf[j][1] = Ksb[nn * KPAD + k0 + t + 4];
            }
            #pragma unroll
            for (int j = 0; j < 4; j++)
                mma_tf32(s[j], qa[ks], bf[j]);
        }

        // ---- warp-uniform max over the 16x32 tile
        float tm = -INFINITY;
        #pragma unroll
        for (int j = 0; j < 4; j++) {
            tm = fmaxf(tm, fmaxf(fmaxf(s[j][0], s[j][1]),
                                 fmaxf(s[j][2], s[j][3])));
        }
        #pragma unroll
        for (int d = 16; d >= 1; d >>= 1)
            tm = fmaxf(tm, __shfl_xor_sync(0xffffffffu, tm, d));

        const float mn = fmaxf(m, tm);
        const float a  = __expf(m - mn);   // warp-uniform
        if (a < 1.f) {                     // uniform branch; skipped when max unchanged
            l0 *= a; l1 *= a;
            #pragma unroll
            for (int j = 0; j < 8; j++) {
                o[j][0] *= a; o[j][1] *= a; o[j][2] *= a; o[j][3] *= a;
            }
        }
        m = mn;

        // ---- exp + P to per-warp smem (A-fragment staging)
        float rs0 = 0.f, rs1 = 0.f;
        #pragma unroll
        for (int j = 0; j < 4; j++) {
            const float p0 = __expf(s[j][0] - m);
            const float p1 = __expf(s[j][1] - m);
            const float p2 = __expf(s[j][2] - m);
            const float p3 = __expf(s[j][3] - m);
            rs0 += p0 + p1;
            rs1 += p2 + p3;
            const int c = j * 8 + 2 * t;
            Pb[pbase + g * PPAD + c]           = tf32r(p0);
            Pb[pbase + g * PPAD + c + 1]       = tf32r(p1);
            Pb[pbase + (g + 8) * PPAD + c]     = tf32r(p2);
            Pb[pbase + (g + 8) * PPAD + c + 1] = tf32r(p3);
        }
        rs0 += __shfl_xor_sync(0xffffffffu, rs0, 1);
        rs0 += __shfl_xor_sync(0xffffffffu, rs0, 2);
        rs1 += __shfl_xor_sync(0xffffffffu, rs1, 1);
        rs1 += __shfl_xor_sync(0xffffffffu, rs1, 2);
        l0 += rs0; l1 += rs1;

        __syncwarp();

        // ---- O[16x64] += P[16x32] @ V[32x64]
        #pragma unroll
        for (int ks = 0; ks < 4; ks++) {
            const int k0 = ks * 8;
            uint32_t pa[4];
            pa[0] = Pb[pbase + g * PPAD + k0 + t];
            pa[1] = Pb[pbase + (g + 8) * PPAD + k0 + t];
            pa[2] = Pb[pbase + g * PPAD + k0 + t + 4];
            pa[3] = Pb[pbase + (g + 8) * PPAD + k0 + t + 4];
            #pragma unroll
            for (int j = 0; j < 8; j++) {
                uint32_t bf[2];
                const int nn = j * 8 + g;
                bf[0] = Vsb[(k0 + t    ) * VPAD + nn];
                bf[1] = Vsb[(k0 + t + 4) * VPAD + nn];
                mma_tf32(o[j], pa, bf);
            }
        }
        __syncwarp();   // P reuse next tile (same warp)

        if (n + 1 < NT) sttile(buf ^ 1, krn, vrn);
        __syncthreads();
    }

    // ---- epilogue
    const float inv0 = 1.f / l0;
    const float inv1 = 1.f / l1;
    float* o0 = O + qg0;
    float* o1 = o0 + 8 * INNER;
    #pragma unroll
    for (int j = 0; j < 8; j++) {
        const int c = j * 8 + 2 * t;
        float2 v0 = { o[j][0] * inv0, o[j][1] * inv0 };
        float2 v1 = { o[j][2] * inv1, o[j][3] * inv1 };
        *(float2*)(o0 + c) = v0;
        *(float2*)(o1 + c) = v1;
    }
}

// ===========================================================================
// kernel_launch
// ===========================================================================
extern "C" void kernel_launch(void* const* d_in, const int* in_sizes, int n_in,
                              void* d_out, int out_size)
{
    const float* x_q   = (const float*)d_in[0];
    const float* x_kv  = (const float*)d_in[1];
    const float* W_qkv = (const float*)d_in[2];  // [1024, 3072]
    const float* W_out = (const float*)d_in[3];  // [1024, 1024]
    const float* b_out = (const float*)d_in[4];  // [1024]
    float* out = (float*)d_out;

    float *q, *kv, *o;
    cudaGetSymbolAddress((void**)&q,  g_q);
    cudaGetSymbolAddress((void**)&kv, g_kv);
    cudaGetSymbolAddress((void**)&o,  g_o);

    cudaFuncSetAttribute(gemm_tf32mma,
                         cudaFuncAttributeMaxDynamicSharedMemorySize, SM_BYTES);
    cudaFuncSetAttribute(attn_tc,
                         cudaFuncAttributeMaxDynamicSharedMemorySize, ATT_SM_BYTES);

    // Q = x_q @ W_qkv[:, 0:1024]             -> [4096, 1024]
    gemm_tf32mma<<<dim3(INNER / 128, MQ / 128), 256, SM_BYTES>>>(
        x_q, W_qkv, q, nullptr, DIM, DIM, 3 * INNER, INNER);

    // KV = x_kv @ W_qkv[:, 1024:3072]        -> [4096, 2048]  (K | V)
    gemm_tf32mma<<<dim3(2 * INNER / 128, MKV / 128), 256, SM_BYTES>>>(
        x_kv, W_qkv + INNER, kv, nullptr, DIM, DIM, 3 * INNER, 2 * INNER);

    // attention (tensor core, fa2)            -> O [4096, 1024]
    attn_tc<<<dim3(SQ / 256, HEADS, BATCH), 512, ATT_SM_BYTES>>>(q, kv, o);

    // out = O @ W_out + b_out                 -> [4096, 1024]
    gemm_tf32mma<<<dim3(DIM / 128, MQ / 128), 256, SM_BYTES>>>(
        o, W_out, out, b_out, INNER, INNER, DIM, DIM);
}